// round 10
// baseline (speedup 1.0000x reference)
#include <cuda_runtime.h>
#include <cstdint>

#define BB 2
#define TT 512
#define CC 128
#define C2 256
#define HS 64

#define SA 16.0f
#define SB 1024.0f
#define INV_SAB (1.0f / (16.0f * 1024.0f))

// ---------------- scratch (no allocations allowed) -------------------------
__device__ float g_K[BB*TT*CC];
__device__ float g_Q[BB*TT*CC];
__device__ float g_V[BB*TT*HS];
__device__ float g_S[(size_t)BB*TT*TT];
// W1^T (n-major) int8, swizzled 256B rows: 128 n x 256 k = 32KB
__device__ __align__(16) unsigned char g_Bimg[32768];

__device__ __forceinline__ uint32_t smem_u32(const void* p) {
    uint32_t a;
    asm("{ .reg .u64 t; cvta.to.shared.u64 t, %1; cvt.u32.u64 %0, t; }" : "=r"(a) : "l"(p));
    return a;
}
// 256B-row layout, swizzled per 128B half so 8 rows hit distinct 16B banks
__device__ __forceinline__ uint32_t swz256(uint32_t row, uint32_t kb) {
    return row*256u + (kb & 128u) + ((kb & 127u) ^ ((row & 7u)*16u));
}
__host__ __device__ __forceinline__ uint32_t swz256_h(uint32_t row, uint32_t kb) {
    return row*256u + (kb & 128u) + ((kb & 127u) ^ ((row & 7u)*16u));
}

__device__ __forceinline__ void ldsm_x4(uint32_t addr, uint32_t& r0, uint32_t& r1,
                                        uint32_t& r2, uint32_t& r3) {
    asm volatile("ldmatrix.sync.aligned.m8n8.x4.shared.b16 {%0,%1,%2,%3}, [%4];"
                 : "=r"(r0), "=r"(r1), "=r"(r2), "=r"(r3) : "r"(addr));
}
__device__ __forceinline__ void imma16832(int* d, const uint32_t* a, uint32_t b0, uint32_t b1) {
    asm volatile("mma.sync.aligned.m16n8k32.row.col.s32.s8.s8.s32 "
                 "{%0,%1,%2,%3}, {%4,%5,%6,%7}, {%8,%9}, {%0,%1,%2,%3};"
                 : "+r"(d[0]), "+r"(d[1]), "+r"(d[2]), "+r"(d[3])
                 : "r"(a[0]), "r"(a[1]), "r"(a[2]), "r"(a[3]), "r"(b0), "r"(b1));
}
__device__ __forceinline__ uint32_t quant4(float4 v, float s) {
    int a0 = __float2int_rn(fminf(fmaxf(v.x*s, -127.f), 127.f));
    int a1 = __float2int_rn(fminf(fmaxf(v.y*s, -127.f), 127.f));
    int a2 = __float2int_rn(fminf(fmaxf(v.z*s, -127.f), 127.f));
    int a3 = __float2int_rn(fminf(fmaxf(v.w*s, -127.f), 127.f));
    return (uint32_t)(a0 & 255) | ((uint32_t)(a1 & 255) << 8)
         | ((uint32_t)(a2 & 255) << 16) | ((uint32_t)(a3 & 255) << 24);
}
// exact gelu via erff (cheap polynomial, no exp path)
__device__ __forceinline__ float gelu_exact(float x) {
    return 0.5f * x * (1.f + erff(x * 0.70710678118654752f));
}

// ---------------------------------------------------------------------------
// Kernel 0: W1 -> W1^T int8 swizzled image (scale SB)
// ---------------------------------------------------------------------------
__global__ void prepB_kernel(const float* __restrict__ W1) {
    int t = blockIdx.x * 256 + threadIdx.x;   // 0 .. 32767
    if (t >= 128*256) return;
    int n = t >> 8;
    int k = t & 255;
    float w = W1[k*CC + n];
    int q = __float2int_rn(fminf(fmaxf(w * SB, -127.f), 127.f));
    g_Bimg[swz256((uint32_t)n, (uint32_t)k)] = (unsigned char)(q & 255);
}

// ---------------------------------------------------------------------------
// Kernel 1: K/Q/V.  4 rows per block, 256 threads, 256 blocks.
// ---------------------------------------------------------------------------
__global__ void kqv_kernel(const float* __restrict__ x,
                           const float* __restrict__ W1,
                           const float* __restrict__ Wv,
                           const float* __restrict__ bv) {
    __shared__ float sx[4][CC];
    int r0 = blockIdx.x * 4;
    int t = threadIdx.x;
    for (int idx = t; idx < 4*CC; idx += 256)
        sx[idx >> 7][idx & 127] = x[(r0 + (idx >> 7))*CC + (idx & 127)];
    __syncthreads();

    int h = t & 127;
    const float* Wcol = (t < 128) ? W1 : (W1 + CC*CC);
    float a[4] = {0.f, 0.f, 0.f, 0.f};
#pragma unroll 8
    for (int d = 0; d < CC; d++) {
        float w = Wcol[d*CC + h];
#pragma unroll
        for (int r = 0; r < 4; r++) a[r] = fmaf(sx[r][d], w, a[r]);
    }
    float* dst = (t < 128) ? g_K : g_Q;
#pragma unroll
    for (int r = 0; r < 4; r++) dst[(r0 + r)*CC + h] = a[r];

    if (t < HS) {
        float v[4];
        float bvh = bv[t];
#pragma unroll
        for (int r = 0; r < 4; r++) v[r] = bvh;
#pragma unroll 8
        for (int d = 0; d < CC; d++) {
            float w = Wv[d*HS + t];
#pragma unroll
            for (int r = 0; r < 4; r++) v[r] = fmaf(sx[r][d], w, v[r]);
        }
#pragma unroll
        for (int r = 0; r < 4; r++) g_V[(r0 + r)*HS + t] = v[r];
    }
}

// ---------------------------------------------------------------------------
// Kernel 2: int8 IMMA (m16n8k32) P-GEMM + erff gelu epilogue
//   block = (i, 64-j tile), 128 threads = 4 warps, warp 16j x 128n
// smem: [0,32K) B image  [32K,48K) A tile (64 x 256B s8)  [48K..) misc
// ---------------------------------------------------------------------------
#define A_OFF 32768
#define MISC  49152
#define SMEM_BYTES (MISC + 2048)

__global__ void __launch_bounds__(128, 4)
score_kernel(const float* __restrict__ pd,
             const float* __restrict__ b1,
             const float* __restrict__ W2,
             const float* __restrict__ b2) {
    int i = blockIdx.x;
    int jbase = blockIdx.y * 64;
    if (jbase > i) return;
    int jmax = (i - jbase < 64) ? (i - jbase) : 63;

    extern __shared__ __align__(16) unsigned char sm[];
    uint32_t base = smem_u32(sm);

    int tid  = threadIdx.x;
    int lane = tid & 31;
    int wid  = tid >> 5;          // 4 warps, each 16 j-rows
    int j0   = wid * 16;
    bool active = (j0 <= jmax);

    float* w2s = (float*)(sm + MISC);          // 128 f
    float* qs  = (float*)(sm + MISC + 512);    // 2 x 128 f
    float b2v  = b2[0];

    if (tid < 128) {
        w2s[tid] = W2[tid];
        float b1h = b1[tid];
        qs[tid]       = g_Q[((size_t)i)*CC + tid]        + b1h;
        qs[128 + tid] = g_Q[((size_t)(TT + i))*CC + tid] + b1h;
    }
    {   // B image -> smem (32KB)
        const float4* src = (const float4*)g_Bimg;
        float4* dst = (float4*)sm;
#pragma unroll
        for (int it = 0; it < 16; it++) dst[tid + it*128] = src[tid + it*128];
    }
    {   // A tile: 64 j x 256 k fp32 -> s8, swizzled
        const float4* prow = (const float4*)(pd + ((size_t)i*TT + jbase)*C2);
#pragma unroll 8
        for (int it = 0; it < 32; it++) {
            int idx = tid + it*128;        // 0..4095
            int j   = idx >> 6;
            int f4  = idx & 63;
            if (j <= jmax) {
                float4 v = prow[j*64 + f4];
                *(uint32_t*)(sm + A_OFF + swz256((uint32_t)j, (uint32_t)f4*4u)) =
                    quant4(v, SA);
            }
        }
    }
    __syncthreads();

    int acc[16][4];
#pragma unroll
    for (int nt = 0; nt < 16; nt++)
#pragma unroll
        for (int r = 0; r < 4; r++) acc[nt][r] = 0;

    if (active) {
#pragma unroll
        for (int ks = 0; ks < 8; ks++) {
            uint32_t kb = (uint32_t)ks*32u;
            uint32_t a[4];
            ldsm_x4(base + A_OFF + swz256((uint32_t)(j0 + (lane & 15)),
                                          kb + ((uint32_t)(lane >> 4))*16u),
                    a[0], a[1], a[2], a[3]);
#pragma unroll
            for (int p = 0; p < 8; p++) {
                uint32_t n  = (uint32_t)(p*16 + (lane & 7) + ((lane >> 4) << 3));
                uint32_t by = kb + ((uint32_t)((lane >> 3) & 1))*16u;
                uint32_t b0, b1r, b2r, b3;
                ldsm_x4(base + swz256(n, by), b0, b1r, b2r, b3);
                imma16832(acc[2*p],     a, b0,  b1r);
                imma16832(acc[2*p + 1], a, b2r, b3);
            }
        }

        // --- epilogue: dequant + q + k, erff gelu, W2 dot, quad reduce
#pragma unroll
        for (int b = 0; b < BB; b++) {
            const float* qb = qs + b*128;
#pragma unroll
            for (int rh = 0; rh < 2; rh++) {
                int j = j0 + (lane >> 2) + 8*rh;
                const float* kb = g_K + ((size_t)(b*TT + jbase + j))*CC;
                float partial = 0.f;
#pragma unroll
                for (int nt = 0; nt < 16; nt++) {
                    int h0 = nt*8 + (lane & 3)*2;
                    float2 kv = *(const float2*)(kb + h0);
                    float pre0 = (float)acc[nt][rh*2 + 0] * INV_SAB + qb[h0]     + kv.x;
                    float pre1 = (float)acc[nt][rh*2 + 1] * INV_SAB + qb[h0 + 1] + kv.y;
                    partial = fmaf(gelu_exact(pre0), w2s[h0],     partial);
                    partial = fmaf(gelu_exact(pre1), w2s[h0 + 1], partial);
                }
                partial += __shfl_xor_sync(0xffffffffu, partial, 1);
                partial += __shfl_xor_sync(0xffffffffu, partial, 2);
                int jg = jbase + j;
                if ((lane & 3) == 0 && jg <= i)
                    g_S[((size_t)(b*TT + i))*TT + jg] = partial + b2v;
            }
        }
    }
}

// ---------------------------------------------------------------------------
// Kernel 3: causal softmax (scaled) + wei @ V, 256 threads
// ---------------------------------------------------------------------------
__global__ void softmax_av_kernel(float* __restrict__ out) {
    int bi = blockIdx.x;
    int b = bi >> 9, i = bi & 511;
    int t = threadIdx.x;
    int n = i + 1;

    __shared__ float p[TT];
    __shared__ float red[256];
    const float scale = 0.088388347648318447f;
    const float* srow = &g_S[((size_t)(b*TT + i))*TT];

    float m = -1e30f;
    for (int j = t; j < n; j += 256) m = fmaxf(m, srow[j]*scale);
    red[t] = m; __syncthreads();
    for (int s = 128; s; s >>= 1) { if (t < s) red[t] = fmaxf(red[t], red[t+s]); __syncthreads(); }
    m = red[0]; __syncthreads();

    float sum = 0.f;
    for (int j = t; j < n; j += 256) {
        float e = expf(srow[j]*scale - m);
        p[j] = e;
        sum += e;
    }
    red[t] = sum; __syncthreads();
    for (int s = 128; s; s >>= 1) { if (t < s) red[t] += red[t+s]; __syncthreads(); }
    float inv = 1.f / red[0];
    __syncthreads();

    int h = t & 63, slice = t >> 6;
    float acc = 0.f;
    for (int j = slice; j < n; j += 4)
        acc = fmaf(p[j], g_V[((size_t)(b*TT + j))*HS + h], acc);
    red[t] = acc; __syncthreads();
    if (t < HS)
        out[((size_t)(b*TT + i))*HS + t] =
            (red[t] + red[t+64] + red[t+128] + red[t+192]) * inv;
}

// ---------------------------------------------------------------------------
extern "C" void kernel_launch(void* const* d_in, const int* in_sizes, int n_in,
                              void* d_out, int out_size) {
    const float* x  = (const float*)d_in[0];
    const float* pd = (const float*)d_in[2];
    const float* W1 = (const float*)d_in[3];
    const float* b1 = (const float*)d_in[4];
    const float* W2 = (const float*)d_in[5];
    const float* b2 = (const float*)d_in[6];
    const float* Wv = (const float*)d_in[7];
    const float* bv = (const float*)d_in[8];
    float* out = (float*)d_out;

    cudaFuncSetAttribute(score_kernel, cudaFuncAttributeMaxDynamicSharedMemorySize, SMEM_BYTES);

    prepB_kernel<<<128, 256>>>(W1);
    kqv_kernel<<<256, 256>>>(x, W1, Wv, bv);
    score_kernel<<<dim3(TT, 8), 128, SMEM_BYTES>>>(pd, b1, W2, b2);
    softmax_av_kernel<<<BB*TT, 256>>>(out);
}

// round 11
// speedup vs baseline: 1.3774x; 1.3774x over previous
#include <cuda_runtime.h>
#include <cuda_fp16.h>
#include <cstdint>

#define BB 2
#define TT 512
#define CC 128
#define C2 256
#define HS 64

// ---------------- scratch (no allocations allowed) -------------------------
__device__ float g_K[BB*TT*CC];
__device__ float g_Q[BB*TT*CC];
__device__ float g_V[BB*TT*HS];
__device__ float g_S[(size_t)BB*TT*TT];
// W1^T (n-major) fp16, swizzled: 4 K-chunks x 16KB
__device__ __align__(16) unsigned char g_Bimg[4*16384];

__device__ __forceinline__ uint32_t smem_u32(const void* p) {
    uint32_t a;
    asm("{ .reg .u64 t; cvta.to.shared.u64 t, %1; cvt.u32.u64 %0, t; }" : "=r"(a) : "l"(p));
    return a;
}
// row-local swizzle: rows are 128B; XOR 16B-bank by (row&7)
#define SWZB(row, kbyte) ((uint32_t)(row)*128u + (((uint32_t)(kbyte)) ^ ((((uint32_t)(row))&7u)*16u)))

__device__ __forceinline__ void ldsm_x4(uint32_t addr, uint32_t& r0, uint32_t& r1,
                                        uint32_t& r2, uint32_t& r3) {
    asm volatile("ldmatrix.sync.aligned.m8n8.x4.shared.b16 {%0,%1,%2,%3}, [%4];"
                 : "=r"(r0), "=r"(r1), "=r"(r2), "=r"(r3) : "r"(addr));
}
// fp16-accumulate HMMA (2 output regs = 4 halves)
__device__ __forceinline__ void mma16816h(uint32_t* d, const uint32_t* a, uint32_t b0, uint32_t b1) {
    asm volatile("mma.sync.aligned.m16n8k16.row.col.f16.f16.f16.f16 "
                 "{%0,%1}, {%2,%3,%4,%5}, {%6,%7}, {%0,%1};"
                 : "+r"(d[0]), "+r"(d[1])
                 : "r"(a[0]), "r"(a[1]), "r"(a[2]), "r"(a[3]), "r"(b0), "r"(b1));
}
// exact gelu via erff (cheap polynomial, no exp path)
__device__ __forceinline__ float gelu_exact(float x) {
    return 0.5f * x * (1.f + erff(x * 0.70710678118654752f));
}

// ---------------------------------------------------------------------------
// Kernel 1: blocks [0,256): K/Q/V (4 rows each).  blocks [256,384): W1 image.
// ---------------------------------------------------------------------------
__global__ void kqv_prep_kernel(const float* __restrict__ x,
                                const float* __restrict__ W1,
                                const float* __restrict__ Wv,
                                const float* __restrict__ bv) {
    if (blockIdx.x >= 256) {
        int t = (blockIdx.x - 256) * 256 + threadIdx.x;   // 0 .. 32767
        int c   = t >> 13;
        int rem = t & 8191;
        int n   = rem >> 6;
        int kk  = rem & 63;
        float w = W1[(c*64 + kk) * CC + n];
        *(__half*)(g_Bimg + c*16384 + SWZB(n, kk*2)) = __float2half_rn(w);
        return;
    }

    __shared__ float sx[4][CC];
    int r0 = blockIdx.x * 4;
    int t = threadIdx.x;
    for (int idx = t; idx < 4*CC; idx += 256)
        sx[idx >> 7][idx & 127] = x[(r0 + (idx >> 7))*CC + (idx & 127)];
    __syncthreads();

    int h = t & 127;
    const float* Wcol = (t < 128) ? W1 : (W1 + CC*CC);
    float a[4] = {0.f, 0.f, 0.f, 0.f};
#pragma unroll 8
    for (int d = 0; d < CC; d++) {
        float w = Wcol[d*CC + h];
#pragma unroll
        for (int r = 0; r < 4; r++) a[r] = fmaf(sx[r][d], w, a[r]);
    }
    float* dst = (t < 128) ? g_K : g_Q;
#pragma unroll
    for (int r = 0; r < 4; r++) dst[(r0 + r)*CC + h] = a[r];

    if (t < HS) {
        float v[4];
        float bvh = bv[t];
#pragma unroll
        for (int r = 0; r < 4; r++) v[r] = bvh;
#pragma unroll 8
        for (int d = 0; d < CC; d++) {
            float w = Wv[d*HS + t];
#pragma unroll
            for (int r = 0; r < 4; r++) v[r] = fmaf(sx[r][d], w, v[r]);
        }
#pragma unroll
        for (int r = 0; r < 4; r++) g_V[(r0 + r)*HS + t] = v[r];
    }
}

// ---------------------------------------------------------------------------
// Kernel 2: fp16 HMMA (fp16 accum) P-GEMM, double-buffered A, causal-masked,
//           erff gelu epilogue.  Compact 1-D grid: 1280 active (i, jt) tiles.
//   block = 256 threads = 8 warps (4 j x 2 n), warp 32x64
// smem: [0,64K) B image  [64K,80K) A buf0  [80K,96K) A buf1  [96K..) misc
// ---------------------------------------------------------------------------
#define A0_OFF 65536
#define A1_OFF 81920
#define MISC   98304
#define SMEM_BYTES (MISC + 4096)

__global__ void __launch_bounds__(256, 2)
score_kernel(const float* __restrict__ pd,
             const float* __restrict__ b1,
             const float* __restrict__ W2,
             const float* __restrict__ b2) {
    // triangular decode: jt row-tile counts 512,384,256,128
    int bid = blockIdx.x;
    int i, jt;
    if (bid < 512)       { i = bid;             jt = 0; }
    else if (bid < 896)  { i = bid - 512 + 128; jt = 1; }
    else if (bid < 1152) { i = bid - 896 + 256; jt = 2; }
    else                 { i = bid - 1152 + 384; jt = 3; }
    int jbase = jt * 128;
    int jmax = (i - jbase < 128) ? (i - jbase) : 127;

    extern __shared__ __align__(16) unsigned char sm[];
    uint32_t base = smem_u32(sm);

    int tid  = threadIdx.x;
    int lane = tid & 31;
    int wid  = tid >> 5;
    int warp_j = wid & 3;    // 4 x 32 rows
    int warp_n = wid >> 2;   // 2 x 64 cols
    bool active = (warp_j * 32 <= jmax);

    float* w2s   = (float*)(sm + MISC);          // 128 f
    float* qs    = (float*)(sm + MISC + 512);    // 2x128 f
    float* partS = (float*)(sm + MISC + 1536);   // 512 f
    float* b2s   = (float*)(sm + MISC + 3584);

    if (tid < 128) w2s[tid] = W2[tid];
    if (tid == 0)  b2s[0] = b2[0];
    {
        int b = tid >> 7, h = tid & 127;
        qs[b*128 + h] = g_Q[((size_t)(b*TT + i))*CC + h] + b1[h];
    }
    {   // B image -> smem (64KB)
        const float4* src = (const float4*)g_Bimg;
        float4* dst = (float4*)sm;
        for (int idx = tid; idx < 4096; idx += 256) dst[idx] = src[idx];
    }

    const float4* prow = (const float4*)(pd + ((size_t)i*TT + jbase)*C2);

#define CONVERT_CHUNK(c, abuf)                                                  \
    do {                                                                        \
        _Pragma("unroll")                                                       \
        for (int it = 0; it < 8; it++) {                                        \
            int idx = tid + it*256;          /* 0..2047 */                      \
            int j   = idx >> 4;                                                 \
            int f4  = idx & 15;                                                 \
            if (j <= jmax) {                                                    \
                float4 v = prow[j*64 + (c)*16 + f4];                            \
                __half2 p0 = __floats2half2_rn(v.x, v.y);                       \
                __half2 p1 = __floats2half2_rn(v.z, v.w);                       \
                unsigned long long h64 =                                        \
                      (unsigned long long)(*(uint32_t*)&p0)                     \
                    | ((unsigned long long)(*(uint32_t*)&p1) << 32);            \
                *(unsigned long long*)(sm + (abuf) + SWZB(j, f4*8)) = h64;      \
            }                                                                   \
        }                                                                       \
    } while (0)

    // fp16 accumulators: [jt2][nt][2 regs = 4 halves]
    uint32_t acc16[2][8][2];
#pragma unroll
    for (int jt2 = 0; jt2 < 2; jt2++)
#pragma unroll
        for (int nt = 0; nt < 8; nt++) { acc16[jt2][nt][0] = 0u; acc16[jt2][nt][1] = 0u; }

    // prologue: chunk 0 into buf0
    CONVERT_CHUNK(0, A0_OFF);
    __syncthreads();

#pragma unroll
    for (int c = 0; c < 4; c++) {
        uint32_t aCur = (c & 1) ? A1_OFF : A0_OFF;
        if (c < 3) {
            uint32_t aNext = (c & 1) ? A0_OFF : A1_OFF;
            CONVERT_CHUNK(c + 1, aNext);
        }

        if (active) {
            uint32_t bBase = base + (uint32_t)c*16384u;
#pragma unroll
            for (int kk = 0; kk < 4; kk++) {
                int k0 = kk*16;
                uint32_t a0[4], a1[4];
                {
                    uint32_t kb = (uint32_t)(k0 + ((lane >> 4) & 1)*8)*2u;
                    int j0 = warp_j*32 + (lane & 15);
                    ldsm_x4(base + aCur + SWZB(j0, kb), a0[0], a0[1], a0[2], a0[3]);
                    int j1 = j0 + 16;
                    ldsm_x4(base + aCur + SWZB(j1, kb), a1[0], a1[1], a1[2], a1[3]);
                }
#pragma unroll
                for (int p = 0; p < 4; p++) {
                    int n = warp_n*64 + p*16 + (lane & 7) + ((lane >> 4) << 3);
                    uint32_t kb = (uint32_t)(k0 + ((lane >> 3) & 1)*8)*2u;
                    uint32_t b0, b1r, b2r, b3;
                    ldsm_x4(bBase + SWZB(n, kb), b0, b1r, b2r, b3);
                    mma16816h(acc16[0][2*p],   a0, b0,  b1r);
                    mma16816h(acc16[0][2*p+1], a0, b2r, b3);
                    mma16816h(acc16[1][2*p],   a1, b0,  b1r);
                    mma16816h(acc16[1][2*p+1], a1, b2r, b3);
                }
            }
        }
        __syncthreads();   // next-buffer writes visible; current buffer free
    }

    // --- epilogue: promote fp16 acc once, erff gelu + W2 dot per batch
    if (active) {
#pragma unroll
        for (int jt2 = 0; jt2 < 2; jt2++)
#pragma unroll
            for (int rh = 0; rh < 2; rh++) {
                int j = warp_j*32 + jt2*16 + (lane >> 2) + 8*rh;
                float2 av[8];
#pragma unroll
                for (int nt = 0; nt < 8; nt++)
                    av[nt] = __half22float2(*(__half2*)&acc16[jt2][nt][rh]);
#pragma unroll
                for (int b = 0; b < BB; b++) {
                    const float* qb = qs + b*128;
                    const float* kb = g_K + ((size_t)(b*TT + jbase + j))*CC;
                    float partial = 0.f;
#pragma unroll
                    for (int nt = 0; nt < 8; nt++) {
                        int h0 = warp_n*64 + nt*8 + (lane & 3)*2;
                        float2 kv = *(const float2*)(kb + h0);
                        float pre0 = av[nt].x + qb[h0]     + kv.x;
                        float pre1 = av[nt].y + qb[h0 + 1] + kv.y;
                        partial = fmaf(gelu_exact(pre0), w2s[h0],     partial);
                        partial = fmaf(gelu_exact(pre1), w2s[h0 + 1], partial);
                    }
                    partial += __shfl_xor_sync(0xffffffffu, partial, 1);
                    partial += __shfl_xor_sync(0xffffffffu, partial, 2);
                    if ((lane & 3) == 0)
                        partS[warp_n*256 + b*128 + j] = partial;
                }
            }
    }
    __syncthreads();

    {
        int b = tid >> 7, j = tid & 127;
        int jg = jbase + j;
        if (jg <= i)
            g_S[((size_t)(b*TT + i))*TT + jg] =
                partS[b*128 + j] + partS[256 + b*128 + j] + b2s[0];
    }
}

// ---------------------------------------------------------------------------
// Kernel 3: causal softmax (scaled) + wei @ V, 256 threads
// ---------------------------------------------------------------------------
__global__ void softmax_av_kernel(float* __restrict__ out) {
    int bi = blockIdx.x;
    int b = bi >> 9, i = bi & 511;
    int t = threadIdx.x;
    int n = i + 1;

    __shared__ float p[TT];
    __shared__ float red[256];
    const float scale = 0.088388347648318447f;
    const float* srow = &g_S[((size_t)(b*TT + i))*TT];

    float m = -1e30f;
    for (int j = t; j < n; j += 256) m = fmaxf(m, srow[j]*scale);
    red[t] = m; __syncthreads();
    for (int s = 128; s; s >>= 1) { if (t < s) red[t] = fmaxf(red[t], red[t+s]); __syncthreads(); }
    m = red[0]; __syncthreads();

    float sum = 0.f;
    for (int j = t; j < n; j += 256) {
        float e = expf(srow[j]*scale - m);
        p[j] = e;
        sum += e;
    }
    red[t] = sum; __syncthreads();
    for (int s = 128; s; s >>= 1) { if (t < s) red[t] += red[t+s]; __syncthreads(); }
    float inv = 1.f / red[0];
    __syncthreads();

    int h = t & 63, slice = t >> 6;
    float acc = 0.f;
    for (int j = slice; j < n; j += 4)
        acc = fmaf(p[j], g_V[((size_t)(b*TT + j))*HS + h], acc);
    red[t] = acc; __syncthreads();
    if (t < HS)
        out[((size_t)(b*TT + i))*HS + t] =
            (red[t] + red[t+64] + red[t+128] + red[t+192]) * inv;
}

// ---------------------------------------------------------------------------
extern "C" void kernel_launch(void* const* d_in, const int* in_sizes, int n_in,
                              void* d_out, int out_size) {
    const float* x  = (const float*)d_in[0];
    const float* pd = (const float*)d_in[2];
    const float* W1 = (const float*)d_in[3];
    const float* b1 = (const float*)d_in[4];
    const float* W2 = (const float*)d_in[5];
    const float* b2 = (const float*)d_in[6];
    const float* Wv = (const float*)d_in[7];
    const float* bv = (const float*)d_in[8];
    float* out = (float*)d_out;

    cudaFuncSetAttribute(score_kernel, cudaFuncAttributeMaxDynamicSharedMemorySize, SMEM_BYTES);

    kqv_prep_kernel<<<384, 256>>>(x, W1, Wv, bv);
    score_kernel<<<1280, 256, SMEM_BYTES>>>(pd, b1, W2, b2);
    softmax_av_kernel<<<BB*TT, 256>>>(out);
}

// round 13
// speedup vs baseline: 1.6454x; 1.1945x over previous
#include <cuda_runtime.h>
#include <cuda_fp16.h>
#include <cstdint>

#define BB 2
#define TT 512
#define CC 128
#define C2 256
#define HS 64

// ---------------- scratch (no allocations allowed) -------------------------
__device__ float g_K[BB*TT*CC];
__device__ float g_Q[BB*TT*CC];
__device__ float g_V[BB*TT*HS];
__device__ float g_S[(size_t)BB*TT*TT];
// W1^T (n-major) fp16, swizzled: 4 K-chunks x 16KB
__device__ __align__(16) unsigned char g_Bimg[4*16384];

__device__ __forceinline__ uint32_t smem_u32(const void* p) {
    uint32_t a;
    asm("{ .reg .u64 t; cvta.to.shared.u64 t, %1; cvt.u32.u64 %0, t; }" : "=r"(a) : "l"(p));
    return a;
}
// row-local swizzle: rows are 128B; XOR 16B-bank by (row&7)
#define SWZB(row, kbyte) ((uint32_t)(row)*128u + (((uint32_t)(kbyte)) ^ ((((uint32_t)(row))&7u)*16u)))

__device__ __forceinline__ void ldsm_x4(uint32_t addr, uint32_t& r0, uint32_t& r1,
                                        uint32_t& r2, uint32_t& r3) {
    asm volatile("ldmatrix.sync.aligned.m8n8.x4.shared.b16 {%0,%1,%2,%3}, [%4];"
                 : "=r"(r0), "=r"(r1), "=r"(r2), "=r"(r3) : "r"(addr));
}
// fp16-accumulate HMMA (2 output regs = 4 halves)
__device__ __forceinline__ void mma16816h(uint32_t* d, const uint32_t* a, uint32_t b0, uint32_t b1) {
    asm volatile("mma.sync.aligned.m16n8k16.row.col.f16.f16.f16.f16 "
                 "{%0,%1}, {%2,%3,%4,%5}, {%6,%7}, {%0,%1};"
                 : "+r"(d[0]), "+r"(d[1])
                 : "r"(a[0]), "r"(a[1]), "r"(a[2]), "r"(a[3]), "r"(b0), "r"(b1));
}
// exact gelu via erff (cheap polynomial, no exp path)
__device__ __forceinline__ float gelu_exact(float x) {
    return 0.5f * x * (1.f + erff(x * 0.70710678118654752f));
}

// ---------------------------------------------------------------------------
// Kernel 1: blocks [0,512): K/Q/V (2 rows each).  blocks [512,640): W1 image.
// ---------------------------------------------------------------------------
__global__ void kqv_prep_kernel(const float* __restrict__ x,
                                const float* __restrict__ W1,
                                const float* __restrict__ Wv,
                                const float* __restrict__ bv) {
    if (blockIdx.x >= 512) {
        int t = (blockIdx.x - 512) * 256 + threadIdx.x;   // 0 .. 32767
        int c   = t >> 13;
        int rem = t & 8191;
        int n   = rem >> 6;
        int kk  = rem & 63;
        float w = W1[(c*64 + kk) * CC + n];
        *(__half*)(g_Bimg + c*16384 + SWZB(n, kk*2)) = __float2half_rn(w);
        return;
    }

    __shared__ float sx[2][CC];
    int r0 = blockIdx.x * 2;
    int t = threadIdx.x;
    if (t < 2*CC)
        sx[t >> 7][t & 127] = x[(r0 + (t >> 7))*CC + (t & 127)];
    __syncthreads();

    int h = t & 127;
    const float* Wcol = (t < 128) ? W1 : (W1 + CC*CC);
    float a0 = 0.f, a1 = 0.f;
#pragma unroll 8
    for (int d = 0; d < CC; d++) {
        float w = Wcol[d*CC + h];
        a0 = fmaf(sx[0][d], w, a0);
        a1 = fmaf(sx[1][d], w, a1);
    }
    float* dst = (t < 128) ? g_K : g_Q;
    dst[(r0    )*CC + h] = a0;
    dst[(r0 + 1)*CC + h] = a1;

    if (t < HS) {
        float bvh = bv[t];
        float v0 = bvh, v1 = bvh;
#pragma unroll 8
        for (int d = 0; d < CC; d++) {
            float w = Wv[d*HS + t];
            v0 = fmaf(sx[0][d], w, v0);
            v1 = fmaf(sx[1][d], w, v1);
        }
        g_V[(r0    )*HS + t] = v0;
        g_V[(r0 + 1)*HS + t] = v1;
    }
}

// ---------------------------------------------------------------------------
// Kernel 2: fp16 HMMA (fp16 accum) P-GEMM, 64-row j tiles, 128 threads,
//           A and B both per-chunk double-buffered -> smem 52KB -> occ 4.
//   4 warps (2 j x 2 n), warp tile 32j x 64n (inner code identical to R8)
// smem: [0,16K) B buf0  [16K,32K) B buf1  [32K,40K) A buf0  [40K,48K) A buf1
//       [48K..) misc
// ---------------------------------------------------------------------------
#define B0_OFF 0
#define B1_OFF 16384
#define A0_OFF 32768
#define A1_OFF 40960
#define MISC   49152
#define SMEM_BYTES (MISC + 4096)

__global__ void __launch_bounds__(128, 4)
score_kernel(const float* __restrict__ pd,
             const float* __restrict__ b1,
             const float* __restrict__ W2,
             const float* __restrict__ b2) {
    int i = blockIdx.x;
    int jbase = blockIdx.y * 64;
    if (jbase > i) return;
    int jmax = (i - jbase < 64) ? (i - jbase) : 63;

    extern __shared__ __align__(16) unsigned char sm[];
    uint32_t base = smem_u32(sm);

    int tid  = threadIdx.x;
    int lane = tid & 31;
    int wid  = tid >> 5;
    int warp_j = wid & 1;    // 2 x 32 rows
    int warp_n = wid >> 1;   // 2 x 64 cols
    bool active = (warp_j * 32 <= jmax);

    float* w2s   = (float*)(sm + MISC);          // 128 f
    float* qs    = (float*)(sm + MISC + 512);    // 2x128 f
    float* partS = (float*)(sm + MISC + 1536);   // 256 f
    float* b2s   = (float*)(sm + MISC + 2560);

    {
        w2s[tid] = W2[tid];
        float b1h = b1[tid];
        qs[tid]       = g_Q[((size_t)i)*CC + tid]        + b1h;
        qs[128 + tid] = g_Q[((size_t)(TT + i))*CC + tid] + b1h;
        if (tid == 0) b2s[0] = b2[0];
    }

    const float4* prow = (const float4*)(pd + ((size_t)i*TT + jbase)*C2);

#define COPY_B(c, bbuf)                                                         \
    do {                                                                        \
        const float4* src = (const float4*)(g_Bimg + (c)*16384);                \
        float4* dst = (float4*)(sm + (bbuf));                                   \
        _Pragma("unroll")                                                       \
        for (int it = 0; it < 8; it++) dst[tid + it*128] = src[tid + it*128];   \
    } while (0)

#define CONVERT_A(c, abuf)                                                      \
    do {                                                                        \
        _Pragma("unroll")                                                       \
        for (int it = 0; it < 8; it++) {                                        \
            int idx = tid + it*128;          /* 0..1023 */                      \
            int j   = idx >> 4;                                                 \
            int f4  = idx & 15;                                                 \
            if (j <= jmax) {                                                    \
                float4 v = __ldcs(prow + j*64 + (c)*16 + f4);                   \
                __half2 p0 = __floats2half2_rn(v.x, v.y);                       \
                __half2 p1 = __floats2half2_rn(v.z, v.w);                       \
                unsigned long long h64 =                                        \
                      (unsigned long long)(*(uint32_t*)&p0)                     \
                    | ((unsigned long long)(*(uint32_t*)&p1) << 32);            \
                *(unsigned long long*)(sm + (abuf) + SWZB(j, f4*8)) = h64;      \
            }                                                                   \
        }                                                                       \
    } while (0)

    // fp16 accumulators: [jt2][nt][2 regs = 4 halves]
    uint32_t acc16[2][8][2];
#pragma unroll
    for (int jt2 = 0; jt2 < 2; jt2++)
#pragma unroll
        for (int nt = 0; nt < 8; nt++) { acc16[jt2][nt][0] = 0u; acc16[jt2][nt][1] = 0u; }

    // prologue: chunk 0
    COPY_B(0, B0_OFF);
    CONVERT_A(0, A0_OFF);
    __syncthreads();

#pragma unroll
    for (int c = 0; c < 4; c++) {
        uint32_t aCur = (c & 1) ? A1_OFF : A0_OFF;
        uint32_t bCur = (c & 1) ? B1_OFF : B0_OFF;
        if (c < 3) {
            uint32_t aNext = (c & 1) ? A0_OFF : A1_OFF;
            uint32_t bNext = (c & 1) ? B0_OFF : B1_OFF;
            COPY_B(c + 1, bNext);
            CONVERT_A(c + 1, aNext);
        }

        if (active) {
            uint32_t bBase = base + bCur;
#pragma unroll
            for (int kk = 0; kk < 4; kk++) {
                int k0 = kk*16;
                uint32_t a0[4], a1[4];
                {
                    uint32_t kb = (uint32_t)(k0 + ((lane >> 4) & 1)*8)*2u;
                    int j0 = warp_j*32 + (lane & 15);
                    ldsm_x4(base + aCur + SWZB(j0, kb), a0[0], a0[1], a0[2], a0[3]);
                    int j1 = j0 + 16;
                    ldsm_x4(base + aCur + SWZB(j1, kb), a1[0], a1[1], a1[2], a1[3]);
                }
#pragma unroll
                for (int p = 0; p < 4; p++) {
                    int n = warp_n*64 + p*16 + (lane & 7) + ((lane >> 4) << 3);
                    uint32_t kb = (uint32_t)(k0 + ((lane >> 3) & 1)*8)*2u;
                    uint32_t b0, b1r, b2r, b3;
                    ldsm_x4(bBase + SWZB(n, kb), b0, b1r, b2r, b3);
                    mma16816h(acc16[0][2*p],   a0, b0,  b1r);
                    mma16816h(acc16[0][2*p+1], a0, b2r, b3);
                    mma16816h(acc16[1][2*p],   a1, b0,  b1r);
                    mma16816h(acc16[1][2*p+1], a1, b2r, b3);
                }
            }
        }
        __syncthreads();
    }

    // --- epilogue: promote fp16 acc once, erff gelu + W2 dot per batch
    if (active) {
#pragma unroll
        for (int jt2 = 0; jt2 < 2; jt2++)
#pragma unroll
            for (int rh = 0; rh < 2; rh++) {
                int j = warp_j*32 + jt2*16 + (lane >> 2) + 8*rh;
                float2 av[8];
#pragma unroll
                for (int nt = 0; nt < 8; nt++)
                    av[nt] = __half22float2(*(__half2*)&acc16[jt2][nt][rh]);
#pragma unroll
                for (int b = 0; b < BB; b++) {
                    const float* qb = qs + b*128;
                    const float* kb = g_K + ((size_t)(b*TT + jbase + j))*CC;
                    float partial = 0.f;
#pragma unroll
                    for (int nt = 0; nt < 8; nt++) {
                        int h0 = warp_n*64 + nt*8 + (lane & 3)*2;
                        float2 kv = *(const float2*)(kb + h0);
                        float pre0 = av[nt].x + qb[h0]     + kv.x;
                        float pre1 = av[nt].y + qb[h0 + 1] + kv.y;
                        partial = fmaf(gelu_exact(pre0), w2s[h0],     partial);
                        partial = fmaf(gelu_exact(pre1), w2s[h0 + 1], partial);
                    }
                    partial += __shfl_xor_sync(0xffffffffu, partial, 1);
                    partial += __shfl_xor_sync(0xffffffffu, partial, 2);
                    if ((lane & 3) == 0)
                        partS[warp_n*128 + b*64 + j] = partial;
                }
            }
    }
    __syncthreads();

    {
        int b = tid >> 6, j = tid & 63;
        int jg = jbase + j;
        if (jg <= i)
            g_S[((size_t)(b*TT + i))*TT + jg] =
                partS[b*64 + j] + partS[128 + b*64 + j] + b2s[0];
    }
}

// ---------------------------------------------------------------------------
// Kernel 3: causal softmax (scaled) + wei @ V, 256 threads
// ---------------------------------------------------------------------------
__global__ void softmax_av_kernel(float* __restrict__ out) {
    int bi = blockIdx.x;
    int b = bi >> 9, i = bi & 511;
    int t = threadIdx.x;
    int n = i + 1;

    __shared__ float p[TT];
    __shared__ float red[256];
    const float scale = 0.088388347648318447f;
    const float* srow = &g_S[((size_t)(b*TT + i))*TT];

    float m = -1e30f;
    for (int j = t; j < n; j += 256) m = fmaxf(m, srow[j]*scale);
    red[t] = m; __syncthreads();
    for (int s = 128; s; s >>= 1) { if (t < s) red[t] = fmaxf(red[t], red[t+s]); __syncthreads(); }
    m = red[0]; __syncthreads();

    float sum = 0.f;
    for (int j = t; j < n; j += 256) {
        float e = expf(srow[j]*scale - m);
        p[j] = e;
        sum += e;
    }
    red[t] = sum; __syncthreads();
    for (int s = 128; s; s >>= 1) { if (t < s) red[t] += red[t+s]; __syncthreads(); }
    float inv = 1.f / red[0];
    __syncthreads();

    int h = t & 63, slice = t >> 6;
    float acc = 0.f;
    for (int j = slice; j < n; j += 4)
        acc = fmaf(p[j], g_V[((size_t)(b*TT + j))*HS + h], acc);
    red[t] = acc; __syncthreads();
    if (t < HS)
        out[((size_t)(b*TT + i))*HS + t] =
            (red[t] + red[t+64] + red[t+128] + red[t+192]) * inv;
}

// ---------------------------------------------------------------------------
extern "C" void kernel_launch(void* const* d_in, const int* in_sizes, int n_in,
                              void* d_out, int out_size) {
    const float* x  = (const float*)d_in[0];
    const float* pd = (const float*)d_in[2];
    const float* W1 = (const float*)d_in[3];
    const float* b1 = (const float*)d_in[4];
    const float* W2 = (const float*)d_in[5];
    const float* b2 = (const float*)d_in[6];
    const float* Wv = (const float*)d_in[7];
    const float* bv = (const float*)d_in[8];
    float* out = (float*)d_out;

    cudaFuncSetAttribute(score_kernel, cudaFuncAttributeMaxDynamicSharedMemorySize, SMEM_BYTES);

    kqv_prep_kernel<<<640, 256>>>(x, W1, Wv, bv);
    score_kernel<<<dim3(TT, 8), 128, SMEM_BYTES>>>(pd, b1, W2, b2);
    softmax_av_kernel<<<BB*TT, 256>>>(out);
}

// round 15
// speedup vs baseline: 1.7028x; 1.0349x over previous
#include <cuda_runtime.h>
#include <cuda_fp16.h>
#include <cstdint>

#define BB 2
#define TT 512
#define CC 128
#define C2 256
#define HS 64

// ---------------- scratch (no allocations allowed) -------------------------
__device__ float g_K[BB*TT*CC];
__device__ float g_Q[BB*TT*CC];
__device__ float g_V[BB*TT*HS];
__device__ float g_S[(size_t)BB*TT*TT];
// W1^T (n-major) fp16, swizzled: 4 K-chunks x 16KB
__device__ __align__(16) unsigned char g_Bimg[4*16384];

__device__ __forceinline__ uint32_t smem_u32(const void* p) {
    uint32_t a;
    asm("{ .reg .u64 t; cvta.to.shared.u64 t, %1; cvt.u32.u64 %0, t; }" : "=r"(a) : "l"(p));
    return a;
}
// row-local swizzle: rows are 128B; XOR 16B-bank by (row&7)
#define SWZB(row, kbyte) ((uint32_t)(row)*128u + (((uint32_t)(kbyte)) ^ ((((uint32_t)(row))&7u)*16u)))

__device__ __forceinline__ void ldsm_x4(uint32_t addr, uint32_t& r0, uint32_t& r1,
                                        uint32_t& r2, uint32_t& r3) {
    asm volatile("ldmatrix.sync.aligned.m8n8.x4.shared.b16 {%0,%1,%2,%3}, [%4];"
                 : "=r"(r0), "=r"(r1), "=r"(r2), "=r"(r3) : "r"(addr));
}
// fp16-accumulate HMMA (2 output regs = 4 halves)
__device__ __forceinline__ void mma16816h(uint32_t* d, const uint32_t* a, uint32_t b0, uint32_t b1) {
    asm volatile("mma.sync.aligned.m16n8k16.row.col.f16.f16.f16.f16 "
                 "{%0,%1}, {%2,%3,%4,%5}, {%6,%7}, {%0,%1};"
                 : "+r"(d[0]), "+r"(d[1])
                 : "r"(a[0]), "r"(a[1]), "r"(a[2]), "r"(a[3]), "r"(b0), "r"(b1));
}
// exact gelu via erff (cheap polynomial, no exp path)
__device__ __forceinline__ float gelu_exact(float x) {
    return 0.5f * x * (1.f + erff(x * 0.70710678118654752f));
}

// ---------------------------------------------------------------------------
// Kernel 1: blocks [0,512): K/Q/V (2 rows each, role-split threads).
//           blocks [512,640): W1 fp16 image.
// ---------------------------------------------------------------------------
__global__ void kqv_prep_kernel(const float* __restrict__ x,
                                const float* __restrict__ W1,
                                const float* __restrict__ Wv,
                                const float* __restrict__ bv) {
    if (blockIdx.x >= 512) {
        int t = (blockIdx.x - 512) * 256 + threadIdx.x;   // 0 .. 32767
        int c   = t >> 13;
        int rem = t & 8191;
        int n   = rem >> 6;
        int kk  = rem & 63;
        float w = W1[(c*64 + kk) * CC + n];
        *(__half*)(g_Bimg + c*16384 + SWZB(n, kk*2)) = __float2half_rn(w);
        return;
    }

    __shared__ float sx[2][CC];
    int r0 = blockIdx.x * 2;
    int t = threadIdx.x;
    if (t < 2*CC)
        sx[t >> 7][t & 127] = x[(r0 + (t >> 7))*CC + (t & 127)];
    __syncthreads();

    if (t < 128) {
        // K (t<64) or Q (t>=64), 2 columns each, 4 independent chains
        int h0 = (t & 63) * 2;
        const float* Wcol = (t < 64) ? W1 : (W1 + CC*CC);
        float a00 = 0.f, a01 = 0.f, a10 = 0.f, a11 = 0.f;
#pragma unroll 8
        for (int d = 0; d < CC; d++) {
            float2 w = *(const float2*)&Wcol[d*CC + h0];
            float x0 = sx[0][d], x1 = sx[1][d];
            a00 = fmaf(x0, w.x, a00);
            a01 = fmaf(x0, w.y, a01);
            a10 = fmaf(x1, w.x, a10);
            a11 = fmaf(x1, w.y, a11);
        }
        float* dst = (t < 64) ? g_K : g_Q;
        *(float2*)&dst[(r0    )*CC + h0] = make_float2(a00, a01);
        *(float2*)&dst[(r0 + 1)*CC + h0] = make_float2(a10, a11);
    } else if (t < 192) {
        int hv = t - 128;
        float bvh = bv[hv];
        float v0 = bvh, v1 = bvh;
#pragma unroll 8
        for (int d = 0; d < CC; d++) {
            float w = Wv[d*HS + hv];
            v0 = fmaf(sx[0][d], w, v0);
            v1 = fmaf(sx[1][d], w, v1);
        }
        g_V[(r0    )*HS + hv] = v0;
        g_V[(r0 + 1)*HS + hv] = v1;
    }
}

// ---------------------------------------------------------------------------
// Kernel 2: fp16 HMMA (fp16 accum) P-GEMM, 64-row j tiles, 128 threads,
//           A and B both per-chunk double-buffered -> smem 52KB -> occ 4.
//   (unchanged from R13 — proven 80us)
// ---------------------------------------------------------------------------
#define B0_OFF 0
#define B1_OFF 16384
#define A0_OFF 32768
#define A1_OFF 40960
#define MISC   49152
#define SMEM_BYTES (MISC + 4096)

__global__ void __launch_bounds__(128, 4)
score_kernel(const float* __restrict__ pd,
             const float* __restrict__ b1,
             const float* __restrict__ W2,
             const float* __restrict__ b2) {
    int i = blockIdx.x;
    int jbase = blockIdx.y * 64;
    if (jbase > i) return;
    int jmax = (i - jbase < 64) ? (i - jbase) : 63;

    extern __shared__ __align__(16) unsigned char sm[];
    uint32_t base = smem_u32(sm);

    int tid  = threadIdx.x;
    int lane = tid & 31;
    int wid  = tid >> 5;
    int warp_j = wid & 1;    // 2 x 32 rows
    int warp_n = wid >> 1;   // 2 x 64 cols
    bool active = (warp_j * 32 <= jmax);

    float* w2s   = (float*)(sm + MISC);          // 128 f
    float* qs    = (float*)(sm + MISC + 512);    // 2x128 f
    float* partS = (float*)(sm + MISC + 1536);   // 256 f
    float* b2s   = (float*)(sm + MISC + 2560);

    {
        w2s[tid] = W2[tid];
        float b1h = b1[tid];
        qs[tid]       = g_Q[((size_t)i)*CC + tid]        + b1h;
        qs[128 + tid] = g_Q[((size_t)(TT + i))*CC + tid] + b1h;
        if (tid == 0) b2s[0] = b2[0];
    }

    const float4* prow = (const float4*)(pd + ((size_t)i*TT + jbase)*C2);

#define COPY_B(c, bbuf)                                                         \
    do {                                                                        \
        const float4* src = (const float4*)(g_Bimg + (c)*16384);                \
        float4* dst = (float4*)(sm + (bbuf));                                   \
        _Pragma("unroll")                                                       \
        for (int it = 0; it < 8; it++) dst[tid + it*128] = src[tid + it*128];   \
    } while (0)

#define CONVERT_A(c, abuf)                                                      \
    do {                                                                        \
        _Pragma("unroll")                                                       \
        for (int it = 0; it < 8; it++) {                                        \
            int idx = tid + it*128;          /* 0..1023 */                      \
            int j   = idx >> 4;                                                 \
            int f4  = idx & 15;                                                 \
            if (j <= jmax) {                                                    \
                float4 v = __ldcs(prow + j*64 + (c)*16 + f4);                   \
                __half2 p0 = __floats2half2_rn(v.x, v.y);                       \
                __half2 p1 = __floats2half2_rn(v.z, v.w);                       \
                unsigned long long h64 =                                        \
                      (unsigned long long)(*(uint32_t*)&p0)                     \
                    | ((unsigned long long)(*(uint32_t*)&p1) << 32);            \
                *(unsigned long long*)(sm + (abuf) + SWZB(j, f4*8)) = h64;      \
            }                                                                   \
        }                                                                       \
    } while (0)

    uint32_t acc16[2][8][2];
#pragma unroll
    for (int jt2 = 0; jt2 < 2; jt2++)
#pragma unroll
        for (int nt = 0; nt < 8; nt++) { acc16[jt2][nt][0] = 0u; acc16[jt2][nt][1] = 0u; }

    COPY_B(0, B0_OFF);
    CONVERT_A(0, A0_OFF);
    __syncthreads();

#pragma unroll
    for (int c = 0; c < 4; c++) {
        uint32_t aCur = (c & 1) ? A1_OFF : A0_OFF;
        uint32_t bCur = (c & 1) ? B1_OFF : B0_OFF;
        if (c < 3) {
            uint32_t aNext = (c & 1) ? A0_OFF : A1_OFF;
            uint32_t bNext = (c & 1) ? B0_OFF : B1_OFF;
            COPY_B(c + 1, bNext);
            CONVERT_A(c + 1, aNext);
        }

        if (active) {
            uint32_t bBase = base + bCur;
#pragma unroll
            for (int kk = 0; kk < 4; kk++) {
                int k0 = kk*16;
                uint32_t a0[4], a1[4];
                {
                    uint32_t kb = (uint32_t)(k0 + ((lane >> 4) & 1)*8)*2u;
                    int j0 = warp_j*32 + (lane & 15);
                    ldsm_x4(base + aCur + SWZB(j0, kb), a0[0], a0[1], a0[2], a0[3]);
                    int j1 = j0 + 16;
                    ldsm_x4(base + aCur + SWZB(j1, kb), a1[0], a1[1], a1[2], a1[3]);
                }
#pragma unroll
                for (int p = 0; p < 4; p++) {
                    int n = warp_n*64 + p*16 + (lane & 7) + ((lane >> 4) << 3);
                    uint32_t kb = (uint32_t)(k0 + ((lane >> 3) & 1)*8)*2u;
                    uint32_t b0, b1r, b2r, b3;
                    ldsm_x4(bBase + SWZB(n, kb), b0, b1r, b2r, b3);
                    mma16816h(acc16[0][2*p],   a0, b0,  b1r);
                    mma16816h(acc16[0][2*p+1], a0, b2r, b3);
                    mma16816h(acc16[1][2*p],   a1, b0,  b1r);
                    mma16816h(acc16[1][2*p+1], a1, b2r, b3);
                }
            }
        }
        __syncthreads();
    }

    if (active) {
#pragma unroll
        for (int jt2 = 0; jt2 < 2; jt2++)
#pragma unroll
            for (int rh = 0; rh < 2; rh++) {
                int j = warp_j*32 + jt2*16 + (lane >> 2) + 8*rh;
                float2 av[8];
#pragma unroll
                for (int nt = 0; nt < 8; nt++)
                    av[nt] = __half22float2(*(__half2*)&acc16[jt2][nt][rh]);
#pragma unroll
                for (int b = 0; b < BB; b++) {
                    const float* qb = qs + b*128;
                    const float* kb = g_K + ((size_t)(b*TT + jbase + j))*CC;
                    float partial = 0.f;
#pragma unroll
                    for (int nt = 0; nt < 8; nt++) {
                        int h0 = warp_n*64 + nt*8 + (lane & 3)*2;
                        float2 kv = *(const float2*)(kb + h0);
                        float pre0 = av[nt].x + qb[h0]     + kv.x;
                        float pre1 = av[nt].y + qb[h0 + 1] + kv.y;
                        partial = fmaf(gelu_exact(pre0), w2s[h0],     partial);
                        partial = fmaf(gelu_exact(pre1), w2s[h0 + 1], partial);
                    }
                    partial += __shfl_xor_sync(0xffffffffu, partial, 1);
                    partial += __shfl_xor_sync(0xffffffffu, partial, 2);
                    if ((lane & 3) == 0)
                        partS[warp_n*128 + b*64 + j] = partial;
                }
            }
    }
    __syncthreads();

    {
        int b = tid >> 6, j = tid & 63;
        int jg = jbase + j;
        if (jg <= i)
            g_S[((size_t)(b*TT + i))*TT + jg] =
                partS[b*64 + j] + partS[128 + b*64 + j] + b2s[0];
    }
}

// ---------------------------------------------------------------------------
// Kernel 3: causal softmax (scaled) + wei @ V, 512 threads, one j per thread
// ---------------------------------------------------------------------------
__global__ void __launch_bounds__(512)
softmax_av_kernel(float* __restrict__ out) {
    int bi = blockIdx.x;
    int b = bi >> 9, i = bi & 511;
    int t = threadIdx.x;
    int lane = t & 31;
    int wid = t >> 5;          // 16 warps
    int n = i + 1;

    __shared__ float p[TT];
    __shared__ float red[16];
    __shared__ float bcast;
    __shared__ float red2[512];
    const float scale = 0.088388347648318447f;
    const float* srow = &g_S[((size_t)(b*TT + i))*TT];

    float sv = (t < n) ? srow[t]*scale : -1e30f;

    // --- max (warp shuffle + 16-wide cross-warp)
    float m = sv;
#pragma unroll
    for (int off = 16; off; off >>= 1)
        m = fmaxf(m, __shfl_xor_sync(0xffffffffu, m, off));
    if (lane == 0) red[wid] = m;
    __syncthreads();
    if (wid == 0) {
        float mm = red[lane & 15];
#pragma unroll
        for (int off = 8; off; off >>= 1)
            mm = fmaxf(mm, __shfl_xor_sync(0xffffffffu, mm, off));
        if (lane == 0) bcast = mm;
    }
    __syncthreads();
    m = bcast;

    // --- exp + sum
    float e = (t < n) ? expf(sv - m) : 0.f;
    p[t] = e;
    float s = e;
#pragma unroll
    for (int off = 16; off; off >>= 1)
        s += __shfl_xor_sync(0xffffffffu, s, off);
    if (lane == 0) red[wid] = s;
    __syncthreads();
    if (wid == 0) {
        float ss = red[lane & 15];
#pragma unroll
        for (int off = 8; off; off >>= 1)
            ss += __shfl_xor_sync(0xffffffffu, ss, off);
        if (lane == 0) bcast = ss;
    }
    __syncthreads();
    float inv = 1.f / bcast;

    // --- AV: 8 j-slices in parallel, h = t&63
    int h = t & 63, slice = t >> 6;
    float acc = 0.f;
    for (int j = slice; j < n; j += 8)
        acc = fmaf(p[j], g_V[((size_t)(b*TT + j))*HS + h], acc);
    red2[t] = acc;
    __syncthreads();
    if (t < HS) {
        float r = 0.f;
#pragma unroll
        for (int sl = 0; sl < 8; sl++) r += red2[sl*64 + t];
        out[((size_t)(b*TT + i))*HS + t] = r * inv;
    }
}

// ---------------------------------------------------------------------------
extern "C" void kernel_launch(void* const* d_in, const int* in_sizes, int n_in,
                              void* d_out, int out_size) {
    const float* x  = (const float*)d_in[0];
    const float* pd = (const float*)d_in[2];
    const float* W1 = (const float*)d_in[3];
    const float* b1 = (const float*)d_in[4];
    const float* W2 = (const float*)d_in[5];
    const float* b2 = (const float*)d_in[6];
    const float* Wv = (const float*)d_in[7];
    const float* bv = (const float*)d_in[8];
    float* out = (float*)d_out;

    cudaFuncSetAttribute(score_kernel, cudaFuncAttributeMaxDynamicSharedMemorySize, SMEM_BYTES);

    kqv_prep_kernel<<<640, 256>>>(x, W1, Wv, bv);
    score_kernel<<<dim3(TT, 8), 128, SMEM_BYTES>>>(pd, b1, W2, b2);
    softmax_av_kernel<<<BB*TT, 512>>>(out);
}